// round 12
// baseline (speedup 1.0000x reference)
#include <cuda_runtime.h>
#include <cuda_fp16.h>
#include <math_constants.h>

#define N_TOK   262144
#define K_CODES 1024
#define D_DIM   64
#define HW      4096
#define CHW     262144
#define Q_ELEMS 16777216
#define GAP_T   5e-4f          // >= 2x worst-case fp16-split+fp32-accum noise bound
#define FIXCAP  65536

typedef unsigned int u32;

// ---------------- scratch (device globals; no allocation allowed) ----------------
__device__ uint4  g_Wpack[8 * 16 * 4 * 32];  // fragment-packed codebook {bh0,bh1,bl0,bl1}
__device__ float  g_wnh[K_CODES];            // 0.5*||w_k||^2 (fp32)
__device__ double g_wnh64[K_CODES];          // 0.5*||w_k||^2 (fp64, for exact repair)
__device__ float  g_counts[K_CODES];
__device__ float  g_dw[K_CODES * D_DIM];
__device__ float  g_neww[K_CODES * D_DIM];
__device__ float  g_loss;
__device__ float  g_n;
__device__ int    g_idx[N_TOK];
__device__ int    g_nfix;
__device__ int4   g_fixlist[FIXCAP];         // {token, k1, k2, tier2?}

// ---------------- helpers ----------------
__device__ __forceinline__ u32 smem_u32(const void* p) {
    u32 a;
    asm("{ .reg .u64 t; cvta.to.shared.u64 t, %1; cvt.u32.u64 %0, t; }" : "=r"(a) : "l"(p));
    return a;
}
#define CP_ASYNC16(dst, src) \
    asm volatile("cp.async.cg.shared.global [%0], [%1], 16;" :: "r"(dst), "l"(src))
#define CP_COMMIT() asm volatile("cp.async.commit_group;" ::: "memory")
#define CP_WAIT(n)  asm volatile("cp.async.wait_group %0;" :: "n"(n) : "memory")

__device__ __forceinline__ u32 h2_bits(__half2 h) {
    return *reinterpret_cast<u32*>(&h);
}
__device__ __forceinline__ void split_pair(float xa, float xb, u32& hi, u32& lo) {
    __half2 h = __floats2half2_rn(xa, xb);
    float2 hf = __half22float2(h);
    __half2 l = __floats2half2_rn(xa - hf.x, xb - hf.y);
    hi = h2_bits(h);
    lo = h2_bits(l);
}
__device__ __forceinline__ void mma16816(float* c, const u32* a, u32 b0, u32 b1) {
    asm("mma.sync.aligned.m16n8k16.row.col.f32.f16.f16.f32 "
        "{%0,%1,%2,%3}, {%4,%5,%6,%7}, {%8,%9}, {%0,%1,%2,%3};"
        : "+f"(c[0]), "+f"(c[1]), "+f"(c[2]), "+f"(c[3])
        : "r"(a[0]), "r"(a[1]), "r"(a[2]), "r"(a[3]), "r"(b0), "r"(b1));
}
__device__ __forceinline__ bool lt2(float s, int k, float s2, int k2) {
    return (s < s2) || (s == s2 && k < k2);
}
// top-3 insert: scores rs1<=rs2<=rs3, packed indices rk12 = (k2<<16)|k1
__device__ __forceinline__ void ins3(float s, int k,
                                     float& rs1, float& rs2, float& rs3, u32& rk12) {
    bool pa = s < rs1;
    bool pb = s < rs2;
    float nrs3 = pb ? rs2 : fminf(rs3, s);
    float nrs2 = pa ? rs1 : fminf(rs2, s);
    u32 ca = (rk12 << 16) | (u32)k;
    u32 cb = ((u32)k << 16) | (rk12 & 0xffffu);
    rk12 = pa ? ca : (pb ? cb : rk12);
    rs1 = fminf(rs1, s);
    rs2 = nrs2;
    rs3 = nrs3;
}

// ---------------- kernel 1: zero + coalesced norms (warp per code) ----------------
__global__ __launch_bounds__(256)
void k_prep(const float* __restrict__ w) {
    const int gt    = blockIdx.x * 256 + threadIdx.x;   // 0..32767
    const int kcode = gt >> 5;
    const int lane  = gt & 31;

    if (gt < K_CODES) g_counts[gt] = 0.f;
    g_dw[gt * 2]     = 0.f;
    g_dw[gt * 2 + 1] = 0.f;
    if (gt == 0) { g_loss = 0.f; g_nfix = 0; }

    float  v1 = w[kcode * 64 + lane];
    float  v2 = w[kcode * 64 + 32 + lane];
    double sd = (double)v1 * v1 + (double)v2 * v2;
#pragma unroll
    for (int off = 16; off > 0; off >>= 1)
        sd += __shfl_xor_sync(0xffffffffu, sd, off);
    if (lane == 0) {
        g_wnh64[kcode] = 0.5 * sd;
        g_wnh[kcode]   = (float)(0.5 * sd);
    }
}

// ---------------- kernel 2: pack codebook into mma B-fragment order --------------
__global__ void k_pack(const float* __restrict__ w) {
    int item = blockIdx.x * 256 + threadIdx.x;    // 0..16383
    int lane = item & 31;
    int kst  = (item >> 5) & 3;
    int nt   = (item >> 7) & 15;
    int kt   = item >> 11;
    int n = kt * 128 + nt * 8 + (lane >> 2);
    int k = kst * 16 + 2 * (lane & 3);
    const float* wr = w + n * 64;
    u32 h0, l0, h1, l1;
    split_pair(wr[k],     wr[k + 1], h0, l0);
    split_pair(wr[k + 8], wr[k + 9], h1, l1);
    g_Wpack[item] = make_uint4(h0, h1, l0, l1);
}

// ---------------- kernel 3: tensor-core distances + top-3 + scatters + flags ------
// SMEM: [0,64K) = A32 (fp32 tile) during setup, then W double buffers (2 x 32K)
//       [64K, 68K) = all 1024 norms   [68K, 69K) = idx_s
#define SM_WN   65536
#define SM_IDX  69632
#define SM_TOT  70656

__global__ __launch_bounds__(256, 2)
void k_argmin(const float* __restrict__ in, float* __restrict__ out_idx_f) {
    extern __shared__ char smem[];
    const u32 sb = smem_u32(smem);
    float* A32   = (float*)smem;
    float* wn_s  = (float*)(smem + SM_WN);
    int*   idx_s = (int*)(smem + SM_IDX);

    const int tid  = threadIdx.x;
    const int warp = tid >> 5;
    const int lane = tid & 31;
    const int g    = lane >> 2;
    const int t    = lane & 3;
    const int token0 = blockIdx.x * 256;
    const int b   = token0 >> 12;
    const int hw0 = token0 & 4095;
    const float* Abase = in + (size_t)b * CHW + hw0;

    // Load A tile [64 d][256 tok] fp32 (coalesced) + all norms.
#pragma unroll
    for (int r = 0; r < 16; r++) {
        int m = r * 256 + tid;
        int d = m >> 6;
        int c = (m & 63) * 4;
        *(float4*)(A32 + d * 256 + c) = *(const float4*)(Abase + (size_t)d * HW + c);
    }
    ((float4*)wn_s)[tid] = ((const float4*)g_wnh)[tid];
    __syncthreads();

    // Build resident A fragments (hi/lo f16x2): 2 m-tiles x 4 k-steps x 4 regs.
    u32 Ah[2][4][4], Al[2][4][4];
#pragma unroll
    for (int mt = 0; mt < 2; mt++) {
        int r0 = warp * 32 + mt * 16 + g;
        int r1 = r0 + 8;
#pragma unroll
        for (int kst = 0; kst < 4; kst++) {
            int kb = kst * 16;
#pragma unroll
            for (int f = 0; f < 4; f++) {
                int row = (f & 1) ? r1 : r0;
                int kk  = kb + 2 * t + ((f >> 1) ? 8 : 0);
                split_pair(A32[kk * 256 + row], A32[(kk + 1) * 256 + row],
                           Ah[mt][kst][f], Al[mt][kst][f]);
            }
        }
    }
    __syncthreads();    // fragments built -> A32 region becomes W double buffers

    // cp.async prefetch of fragment-packed W tiles (raw copy, 8 x 16B per thread)
    auto prefetch = [&](int chunk, int buf) {
        u32 dst = sb + buf * 32768 + tid * 16;
        const uint4* src = g_Wpack + chunk * 2048 + tid;
#pragma unroll
        for (int r = 0; r < 8; r++)
            CP_ASYNC16(dst + r * 4096, (const void*)(src + r * 256));
    };

    float rs1[4], rs2[4], rs3[4];
    u32   rk12[4];
#pragma unroll
    for (int i = 0; i < 4; i++) {
        rs1[i] = CUDART_INF_F; rs2[i] = CUDART_INF_F; rs3[i] = CUDART_INF_F; rk12[i] = 0;
    }

    prefetch(0, 0);
    CP_COMMIT();

    for (int kt = 0; kt < 8; kt++) {
        if (kt < 7) {
            prefetch(kt + 1, (kt + 1) & 1);
            CP_COMMIT();
            CP_WAIT(1);                 // tile kt landed
        } else {
            CP_WAIT(0);
        }
        __syncthreads();
        const uint4* Wt4 = (const uint4*)(smem + (kt & 1) * 32768);

        // 2 n-tiles per iteration -> 4 independent accumulator chains
        for (int ntp = 0; ntp < 8; ntp++) {
            const int ntA = ntp * 2;
            const int ntB = ntp * 2 + 1;
            float cA0[4] = {0.f, 0.f, 0.f, 0.f};
            float cA1[4] = {0.f, 0.f, 0.f, 0.f};
            float cB0[4] = {0.f, 0.f, 0.f, 0.f};
            float cB1[4] = {0.f, 0.f, 0.f, 0.f};
#pragma unroll
            for (int kst = 0; kst < 4; kst++) {
                uint4 bpA = Wt4[(ntA * 4 + kst) * 32 + lane];
                uint4 bpB = Wt4[(ntB * 4 + kst) * 32 + lane];
                // round-robin across 4 chains; per-chain order hh, lh, hl (unchanged)
                mma16816(cA0, Ah[0][kst], bpA.x, bpA.y);
                mma16816(cB0, Ah[0][kst], bpB.x, bpB.y);
                mma16816(cA1, Ah[1][kst], bpA.x, bpA.y);
                mma16816(cB1, Ah[1][kst], bpB.x, bpB.y);
                mma16816(cA0, Al[0][kst], bpA.x, bpA.y);
                mma16816(cB0, Al[0][kst], bpB.x, bpB.y);
                mma16816(cA1, Al[1][kst], bpA.x, bpA.y);
                mma16816(cB1, Al[1][kst], bpB.x, bpB.y);
                mma16816(cA0, Ah[0][kst], bpA.z, bpA.w);
                mma16816(cB0, Ah[0][kst], bpB.z, bpB.w);
                mma16816(cA1, Ah[1][kst], bpA.z, bpA.w);
                mma16816(cB1, Ah[1][kst], bpB.z, bpB.w);
            }
            // epilogue for both n-tiles
            int nbA = kt * 128 + ntA * 8;
            int nbB = kt * 128 + ntB * 8;
            float waA = wn_s[nbA + 2 * t], wbA = wn_s[nbA + 2 * t + 1];
            float waB = wn_s[nbB + 2 * t], wbB = wn_s[nbB + 2 * t + 1];
            int   kaA = nbA + 2 * t, kaB = nbB + 2 * t;
#pragma unroll
            for (int rr = 0; rr < 4; rr++) {
                const float* ccA = (rr < 2) ? cA0 : cA1;
                const float* ccB = (rr < 2) ? cB0 : cB1;
                int hi = (rr & 1) ? 2 : 0;
                ins3(waA - ccA[hi],     kaA,     rs1[rr], rs2[rr], rs3[rr], rk12[rr]);
                ins3(wbA - ccA[hi + 1], kaA + 1, rs1[rr], rs2[rr], rs3[rr], rk12[rr]);
                ins3(waB - ccB[hi],     kaB,     rs1[rr], rs2[rr], rs3[rr], rk12[rr]);
                ins3(wbB - ccB[hi + 1], kaB + 1, rs1[rr], rs2[rr], rs3[rr], rk12[rr]);
            }
        }
        __syncthreads();    // all warps done with this buffer before prefetch reuses it
    }

    // merge top-3 across the 4-lane column group
#pragma unroll
    for (int rr = 0; rr < 4; rr++) {
#pragma unroll
        for (int off = 1; off <= 2; off <<= 1) {
            float o1 = __shfl_xor_sync(0xffffffffu, rs1[rr], off, 4);
            float o2 = __shfl_xor_sync(0xffffffffu, rs2[rr], off, 4);
            float o3 = __shfl_xor_sync(0xffffffffu, rs3[rr], off, 4);
            u32   oj = __shfl_xor_sync(0xffffffffu, rk12[rr], off, 4);
            int j1 = oj & 0xffff, j2 = oj >> 16;
            float a1 = rs1[rr], a2 = rs2[rr], a3 = rs3[rr];
            int ak1 = rk12[rr] & 0xffff, ak2 = rk12[rr] >> 16;
            if (lt2(o1, j1, a1, ak1)) {
                rs1[rr] = o1;
                if (lt2(a1, ak1, o2, j2)) {
                    rk12[rr] = ((u32)ak1 << 16) | (u32)j1;
                    rs2[rr] = a1; rs3[rr] = fminf(a2, o2);
                } else {
                    rk12[rr] = ((u32)j2 << 16) | (u32)j1;
                    rs2[rr] = o2; rs3[rr] = fminf(a1, o3);
                }
            } else {
                if (lt2(o1, j1, a2, ak2)) {
                    rk12[rr] = ((u32)j1 << 16) | (u32)ak1;
                    rs2[rr] = o1; rs3[rr] = fminf(a2, o2);
                } else {
                    rs3[rr] = fminf(o1, a3);
                }
            }
        }
    }
    __syncthreads();
    if (t == 0) {
#pragma unroll
        for (int rr = 0; rr < 4; rr++) {
            int L = warp * 32 + (rr >> 1) * 16 + (rr & 1) * 8 + g;
            int k1 = rk12[rr] & 0xffff;
            idx_s[L] = k1;
            if (rs2[rr] - rs1[rr] < GAP_T) {
                int tier2 = (rs3[rr] - rs1[rr] < GAP_T) ? 1 : 0;
                int pos = atomicAdd(&g_nfix, 1);
                if (pos < FIXCAP)
                    g_fixlist[pos] = make_int4(token0 + L, k1, (int)(rk12[rr] >> 16), tier2);
            }
        }
    }
    __syncthreads();

    {
        int k = idx_s[tid];
        atomicAdd(&g_counts[k], 1.0f);
        g_idx[token0 + tid]     = k;
        out_idx_f[token0 + tid] = (float)k;
    }

    // dw scatter: re-read A from global (L2-warm), v4 vector reductions.
#pragma unroll
    for (int it = 0; it < 16; it++) {
        int m   = it * 256 + tid;
        int tkn = m & 255;
        int q   = m >> 8;
        float a0 = Abase[(size_t)(q * 4 + 0) * HW + tkn];
        float a1 = Abase[(size_t)(q * 4 + 1) * HW + tkn];
        float a2 = Abase[(size_t)(q * 4 + 2) * HW + tkn];
        float a3 = Abase[(size_t)(q * 4 + 3) * HW + tkn];
        float* p = g_dw + idx_s[tkn] * 64 + q * 4;
        asm volatile("red.global.add.v4.f32 [%0], {%1, %2, %3, %4};"
                     :: "l"(p), "f"(a0), "f"(a1), "f"(a2), "f"(a3) : "memory");
    }
}

// ---------------- kernel 3b: two-tier fp64 repair ----------------
__global__ __launch_bounds__(256)
void k_fix4(const float* __restrict__ in, const float* __restrict__ w,
            float* __restrict__ out_idx_f) {
    __shared__ float xs[8][64];
    int n = g_nfix; if (n > FIXCAP) n = FIXCAP;
    const int warp = threadIdx.x >> 5;
    const int lane = threadIdx.x & 31;
    for (int i = blockIdx.x * 8 + warp; i < n; i += gridDim.x * 8) {
        int4 e = g_fixlist[i];
        const int t = e.x;
        const float* x = in + (size_t)(t >> 12) * CHW + (t & 4095);
        float xv1f = x[(size_t)lane * HW];
        float xv2f = x[(size_t)(lane + 32) * HW];

        int bk;
        if (!e.w) {
            double xv1 = (double)xv1f, xv2 = (double)xv2f;
            double d1 = xv1 * (double)w[e.y * 64 + lane]
                      + xv2 * (double)w[e.y * 64 + 32 + lane];
            double d2 = xv1 * (double)w[e.z * 64 + lane]
                      + xv2 * (double)w[e.z * 64 + 32 + lane];
#pragma unroll
            for (int off = 16; off > 0; off >>= 1) {
                d1 += __shfl_xor_sync(0xffffffffu, d1, off);
                d2 += __shfl_xor_sync(0xffffffffu, d2, off);
            }
            double s1 = g_wnh64[e.y] - d1;
            double s2 = g_wnh64[e.z] - d2;
            bk = (s2 < s1 || (s2 == s1 && e.z < e.y)) ? e.z : e.y;
        } else {
            xs[warp][lane]      = xv1f;
            xs[warp][lane + 32] = xv2f;
            __syncwarp();
            double bd = CUDART_INF;
            bk = 0x7fffffff;
            for (int jj = 0; jj < 8; jj++) {
                int    c[4];
                double acc[4] = {0.0, 0.0, 0.0, 0.0};
#pragma unroll
                for (int u = 0; u < 4; u++) c[u] = (jj + u * 8) * 32 + lane;
#pragma unroll 4
                for (int q = 0; q < 16; q++) {
                    float4 wv[4];
#pragma unroll
                    for (int u = 0; u < 4; u++)
                        wv[u] = ((const float4*)(w + c[u] * 64))[q];
#pragma unroll
                    for (int r = 0; r < 4; r++) {
                        double xv = (double)xs[warp][q * 4 + r];
#pragma unroll
                        for (int u = 0; u < 4; u++)
                            acc[u] = fma(xv, (double)((&wv[u].x)[r]), acc[u]);
                    }
                }
#pragma unroll
                for (int u = 0; u < 4; u++) {
                    double s = g_wnh64[c[u]] - acc[u];
                    if (s < bd || (s == bd && c[u] < bk)) { bd = s; bk = c[u]; }
                }
            }
#pragma unroll
            for (int off = 16; off > 0; off >>= 1) {
                double od = __shfl_xor_sync(0xffffffffu, bd, off);
                int    ok = __shfl_xor_sync(0xffffffffu, bk, off);
                if (od < bd || (od == bd && ok < bk)) { bd = od; bk = ok; }
            }
            __syncwarp();
        }

        int old = e.y;
        if (bk != old) {
            if (lane == 0) {
                g_idx[t]     = bk;
                out_idx_f[t] = (float)bk;
                atomicAdd(&g_counts[old], -1.0f);
                atomicAdd(&g_counts[bk],   1.0f);
            }
            atomicAdd(&g_dw[old * 64 + lane],      -xv1f);
            atomicAdd(&g_dw[old * 64 + 32 + lane], -xv2f);
            atomicAdd(&g_dw[bk  * 64 + lane],       xv1f);
            atomicAdd(&g_dw[bk  * 64 + 32 + lane],  xv2f);
        }
    }
}

// ---------------- kernel 4a: n = sum(cs) ----------------
__global__ void k_sum(const float* __restrict__ ecs) {
    __shared__ float red[1024];
    int k = threadIdx.x;
    red[k] = ecs[k] * 0.99f + 0.01f * g_counts[k];
    __syncthreads();
    for (int s = 512; s > 0; s >>= 1) {
        if (k < s) red[k] += red[k + s];
        __syncthreads();
    }
    if (k == 0) g_n = red[0];
}

// ---------------- kernel 4b: EMA update, fully coalesced ----------------
__global__ __launch_bounds__(256)
void k_updw(const float* __restrict__ ecs, const float* __restrict__ ew) {
    int i = blockIdx.x * 256 + threadIdx.x;
    int k = i >> 6;
    float n  = g_n;
    float cs = ecs[k] * 0.99f + 0.01f * g_counts[k];
    float csn = (cs + 1e-5f) / (n + 1024.0f * 1e-5f) * n;
    float e = ew[i] * 0.99f + 0.01f * g_dw[i];
    g_neww[i] = e / csn;
}

// ---------------- kernel 5: gather + straight-through + loss partials -------------
__global__ __launch_bounds__(256)
void k_gather(const float* __restrict__ in, float* __restrict__ out_q) {
    __shared__ float q_s[128 * 68];
    __shared__ int   idx_s[128];
    __shared__ float part[8];
    const int tid = threadIdx.x;
    const int token0 = blockIdx.x * 128;
    const int b   = token0 >> 12;
    const int hw0 = token0 & 4095;

    if (tid < 128) idx_s[tid] = g_idx[token0 + tid];
    __syncthreads();

#pragma unroll
    for (int r = 0; r < 8; r++) {
        int m  = r * 256 + tid;
        int t  = m >> 4;
        int sg = (m & 15) * 4;
        float4 v = *(const float4*)(g_neww + idx_s[t] * 64 + sg);
        *(float4*)(q_s + t * 68 + sg) = v;
    }
    __syncthreads();

    const size_t base = (size_t)b * CHW + hw0;
    float lsum = 0.f;
#pragma unroll 4
    for (int it = 0; it < 32; it++) {
        int d = it * 2 + (tid >> 7);
        int t = tid & 127;
        size_t gidx = base + (size_t)d * HW + t;
        float x  = in[gidx];
        float q  = q_s[t * 68 + d];
        float dt = q - x;
        out_q[gidx] = x + dt;
        lsum = fmaf(dt, dt, lsum);
    }
#pragma unroll
    for (int off = 16; off > 0; off >>= 1)
        lsum += __shfl_xor_sync(0xffffffffu, lsum, off);
    if ((tid & 31) == 0) part[tid >> 5] = lsum;
    __syncthreads();
    if (tid == 0) {
        float s = 0.f;
#pragma unroll
        for (int i = 0; i < 8; i++) s += part[i];
        atomicAdd(&g_loss, s);
    }
}

// ---------------- kernel 6: finalize loss ----------------
__global__ void k_final(float* out) {
    out[0] = 0.25f * (g_loss * (1.0f / 16777216.0f));
}

// ---------------- launch ----------------
extern "C" void kernel_launch(void* const* d_in, const int* in_sizes, int n_in,
                              void* d_out, int out_size) {
    const float* in  = (const float*)d_in[0];   // (64,64,64,64) NCHW
    const float* w   = (const float*)d_in[1];   // (1024,64)
    const float* ecs = (const float*)d_in[2];   // (1024,)
    const float* ew  = (const float*)d_in[3];   // (1024,64)
    float* out      = (float*)d_out;            // [loss | quantized NCHW | idx]
    float* out_q    = out + 1;
    float* out_idx  = out + 1 + Q_ELEMS;

    k_prep<<<128, 256>>>(w);
    k_pack<<<64, 256>>>(w);
    cudaFuncSetAttribute(k_argmin, cudaFuncAttributeMaxDynamicSharedMemorySize, SM_TOT);
    k_argmin<<<N_TOK / 256, 256, SM_TOT>>>(in, out_idx);
    k_fix4<<<256, 256>>>(in, w, out_idx);
    k_sum<<<1, 1024>>>(ecs);
    k_updw<<<256, 256>>>(ecs, ew);
    k_gather<<<N_TOK / 128, 256>>>(in, out_q);
    k_final<<<1, 1>>>(out);
}

// round 13
// speedup vs baseline: 1.1313x; 1.1313x over previous
#include <cuda_runtime.h>
#include <cuda_fp16.h>
#include <math_constants.h>

#define N_TOK   262144
#define K_CODES 1024
#define D_DIM   64
#define HW      4096
#define CHW     262144
#define Q_ELEMS 16777216
#define GAP_T   5e-4f          // >= 2x (mma eps 1e-5 + quant eps 3.05e-5), 6x margin
#define FIXCAP  65536

typedef unsigned int u32;

// ---------------- scratch (device globals; no allocation allowed) ----------------
__device__ uint4  g_Wpack[8 * 16 * 4 * 32];  // fragment-packed codebook {bh0,bh1,bl0,bl1}
__device__ float  g_wn512[K_CODES];          // 0.5*||w_k||^2 + 512 (magic-biased)
__device__ double g_wnh64[K_CODES];          // 0.5*||w_k||^2 (fp64, for exact repair)
__device__ float  g_counts[K_CODES];
__device__ float  g_dw[K_CODES * D_DIM];
__device__ float  g_neww[K_CODES * D_DIM];
__device__ float  g_loss;
__device__ float  g_n;
__device__ int    g_idx[N_TOK];
__device__ int    g_nfix;
__device__ int4   g_fixlist[FIXCAP];         // {token, k1, k2, tier2?}

// ---------------- helpers ----------------
__device__ __forceinline__ u32 smem_u32(const void* p) {
    u32 a;
    asm("{ .reg .u64 t; cvta.to.shared.u64 t, %1; cvt.u32.u64 %0, t; }" : "=r"(a) : "l"(p));
    return a;
}
#define CP_ASYNC16(dst, src) \
    asm volatile("cp.async.cg.shared.global [%0], [%1], 16;" :: "r"(dst), "l"(src))
#define CP_COMMIT() asm volatile("cp.async.commit_group;" ::: "memory")
#define CP_WAIT(n)  asm volatile("cp.async.wait_group %0;" :: "n"(n) : "memory")

__device__ __forceinline__ u32 h2_bits(__half2 h) {
    return *reinterpret_cast<u32*>(&h);
}
__device__ __forceinline__ void split_pair(float xa, float xb, u32& hi, u32& lo) {
    __half2 h = __floats2half2_rn(xa, xb);
    float2 hf = __half22float2(h);
    __half2 l = __floats2half2_rn(xa - hf.x, xb - hf.y);
    hi = h2_bits(h);
    lo = h2_bits(l);
}
__device__ __forceinline__ void mma16816(float* c, const u32* a, u32 b0, u32 b1) {
    asm("mma.sync.aligned.m16n8k16.row.col.f32.f16.f16.f32 "
        "{%0,%1,%2,%3}, {%4,%5,%6,%7}, {%8,%9}, {%0,%1,%2,%3};"
        : "+f"(c[0]), "+f"(c[1]), "+f"(c[2]), "+f"(c[3])
        : "r"(a[0]), "r"(a[1]), "r"(a[2]), "r"(a[3]), "r"(b0), "r"(b1));
}
__device__ __forceinline__ bool lt2(float s, int k, float s2, int k2) {
    return (s < s2) || (s == s2 && k < k2);
}
// float-domain top-3 insert (used only 24x/thread at kt merges)
__device__ __forceinline__ void ins3(float s, int k,
                                     float& rs1, float& rs2, float& rs3, u32& rk12) {
    bool pa = s < rs1;
    bool pb = s < rs2;
    float nrs3 = pb ? rs2 : fminf(rs3, s);
    float nrs2 = pa ? rs1 : fminf(rs2, s);
    u32 ca = (rk12 << 16) | (u32)k;
    u32 cb = ((u32)k << 16) | (rk12 & 0xffffu);
    rk12 = pa ? ca : (pb ? cb : rk12);
    rs1 = fminf(rs1, s);
    rs2 = nrs2;
    rs3 = nrs3;
}
// integer-key top-3: 5 IMNMX
__device__ __forceinline__ void ikey3(int k, int& n1, int& n2, int& n3) {
    int t1 = max(n1, k);
    n1 = min(n1, k);
    int t2 = max(n2, t1);
    n2 = min(n2, t1);
    n3 = min(n3, t2);
}
// key = float_bits(s512)*32 + c5 - 0x70000000*32  (wraparound-exact, positive result)
__device__ __forceinline__ int mk_key(float s512, int c5) {
    return __float_as_int(s512) * 32 + (int)((u32)c5 + 0x90000000u);
}
__device__ __forceinline__ float un_key(int key) {       // quantized s (unbiased)
    return __int_as_float((key >> 5) + 0x43800000) - 512.0f;
}

// ---------------- kernel 1: zero + coalesced norms (warp per code) ----------------
__global__ __launch_bounds__(256)
void k_prep(const float* __restrict__ w) {
    const int gt    = blockIdx.x * 256 + threadIdx.x;   // 0..32767
    const int kcode = gt >> 5;
    const int lane  = gt & 31;

    if (gt < K_CODES) g_counts[gt] = 0.f;
    g_dw[gt * 2]     = 0.f;
    g_dw[gt * 2 + 1] = 0.f;
    if (gt == 0) { g_loss = 0.f; g_nfix = 0; }

    float  v1 = w[kcode * 64 + lane];
    float  v2 = w[kcode * 64 + 32 + lane];
    double sd = (double)v1 * v1 + (double)v2 * v2;
#pragma unroll
    for (int off = 16; off > 0; off >>= 1)
        sd += __shfl_xor_sync(0xffffffffu, sd, off);
    if (lane == 0) {
        g_wnh64[kcode]  = 0.5 * sd;
        g_wn512[kcode]  = (float)(0.5 * sd) + 512.0f;
    }
}

// ---------------- kernel 2: pack codebook into mma B-fragment order --------------
__global__ void k_pack(const float* __restrict__ w) {
    int item = blockIdx.x * 256 + threadIdx.x;    // 0..16383
    int lane = item & 31;
    int kst  = (item >> 5) & 3;
    int nt   = (item >> 7) & 15;
    int kt   = item >> 11;
    int n = kt * 128 + nt * 8 + (lane >> 2);
    int k = kst * 16 + 2 * (lane & 3);
    const float* wr = w + n * 64;
    u32 h0, l0, h1, l1;
    split_pair(wr[k],     wr[k + 1], h0, l0);
    split_pair(wr[k + 8], wr[k + 9], h1, l1);
    g_Wpack[item] = make_uint4(h0, h1, l0, l1);
}

// ---------------- kernel 3: tensor-core distances + int-key top-3 + scatters ------
// SMEM: [0,64K) = A32 (fp32 tile) during setup, then W double buffers (2 x 32K)
//       [64K, 68K) = wn512 table   [68K, 69K) = idx_s
#define SM_WN   65536
#define SM_IDX  69632
#define SM_TOT  70656

__global__ __launch_bounds__(256, 2)
void k_argmin(const float* __restrict__ in, float* __restrict__ out_idx_f) {
    extern __shared__ char smem[];
    const u32 sb = smem_u32(smem);
    float* A32   = (float*)smem;
    float* wn_s  = (float*)(smem + SM_WN);
    int*   idx_s = (int*)(smem + SM_IDX);

    const int tid  = threadIdx.x;
    const int warp = tid >> 5;
    const int lane = tid & 31;
    const int g    = lane >> 2;
    const int t    = lane & 3;
    const int token0 = blockIdx.x * 256;
    const int b   = token0 >> 12;
    const int hw0 = token0 & 4095;
    const float* Abase = in + (size_t)b * CHW + hw0;

    // Load A tile [64 d][256 tok] fp32 (coalesced) + biased norm table.
#pragma unroll
    for (int r = 0; r < 16; r++) {
        int m = r * 256 + tid;
        int d = m >> 6;
        int c = (m & 63) * 4;
        *(float4*)(A32 + d * 256 + c) = *(const float4*)(Abase + (size_t)d * HW + c);
    }
    ((float4*)wn_s)[tid] = ((const float4*)g_wn512)[tid];
    __syncthreads();

    // Build resident A fragments (hi/lo f16x2): 2 m-tiles x 4 k-steps x 4 regs.
    u32 Ah[2][4][4], Al[2][4][4];
#pragma unroll
    for (int mt = 0; mt < 2; mt++) {
        int r0 = warp * 32 + mt * 16 + g;
        int r1 = r0 + 8;
#pragma unroll
        for (int kst = 0; kst < 4; kst++) {
            int kb = kst * 16;
#pragma unroll
            for (int f = 0; f < 4; f++) {
                int row = (f & 1) ? r1 : r0;
                int kk  = kb + 2 * t + ((f >> 1) ? 8 : 0);
                split_pair(A32[kk * 256 + row], A32[(kk + 1) * 256 + row],
                           Ah[mt][kst][f], Al[mt][kst][f]);
            }
        }
    }
    __syncthreads();    // fragments built -> A32 region becomes W double buffers

    // cp.async prefetch of fragment-packed W tiles (raw copy, 8 x 16B per thread)
    auto prefetch = [&](int chunk, int buf) {
        u32 dst = sb + buf * 32768 + tid * 16;
        const uint4* src = g_Wpack + chunk * 2048 + tid;
#pragma unroll
        for (int r = 0; r < 8; r++)
            CP_ASYNC16(dst + r * 4096, (const void*)(src + r * 256));
    };

    // global top-3 (float domain, merged at kt boundaries)
    float rs1[4], rs2[4], rs3[4];
    u32   rk12[4];
#pragma unroll
    for (int i = 0; i < 4; i++) {
        rs1[i] = CUDART_INF_F; rs2[i] = CUDART_INF_F; rs3[i] = CUDART_INF_F; rk12[i] = 0;
    }

    prefetch(0, 0);
    CP_COMMIT();

    for (int kt = 0; kt < 8; kt++) {
        if (kt < 7) {
            prefetch(kt + 1, (kt + 1) & 1);
            CP_COMMIT();
            CP_WAIT(1);                 // tile kt landed
        } else {
            CP_WAIT(0);
        }
        __syncthreads();
        const uint4* Wt4 = (const uint4*)(smem + (kt & 1) * 32768);

        // per-kt integer-key top-3 (local 5-bit code = nt*2 + which)
        int n1[4], n2[4], n3[4];
#pragma unroll
        for (int i = 0; i < 4; i++) { n1[i] = 0x7fffffff; n2[i] = 0x7fffffff; n3[i] = 0x7fffffff; }

        for (int nt = 0; nt < 16; nt++) {
            float c0[4] = {0.f, 0.f, 0.f, 0.f};
            float c1[4] = {0.f, 0.f, 0.f, 0.f};
#pragma unroll
            for (int kst = 0; kst < 4; kst++) {
                uint4 bp = Wt4[(nt * 4 + kst) * 32 + lane];
                mma16816(c0, Ah[0][kst], bp.x, bp.y);   // ah*bh
                mma16816(c0, Al[0][kst], bp.x, bp.y);   // al*bh
                mma16816(c0, Ah[0][kst], bp.z, bp.w);   // ah*bl
                mma16816(c1, Ah[1][kst], bp.x, bp.y);
                mma16816(c1, Al[1][kst], bp.x, bp.y);
                mma16816(c1, Ah[1][kst], bp.z, bp.w);
            }
            float wa = wn_s[kt * 128 + nt * 8 + 2 * t];       // wn + 512
            float wb = wn_s[kt * 128 + nt * 8 + 2 * t + 1];
#pragma unroll
            for (int rr = 0; rr < 4; rr++) {
                const float* cc = (rr < 2) ? c0 : c1;
                int hi = (rr & 1) ? 2 : 0;
                ikey3(mk_key(wa - cc[hi],     nt * 2),     n1[rr], n2[rr], n3[rr]);
                ikey3(mk_key(wb - cc[hi + 1], nt * 2 + 1), n1[rr], n2[rr], n3[rr]);
            }
        }

        // merge kt-local integer top-3 into global float top-3
#pragma unroll
        for (int rr = 0; rr < 4; rr++) {
            int c5a = n1[rr] & 31, c5b = n2[rr] & 31, c5c = n3[rr] & 31;
            ins3(un_key(n1[rr]), kt * 128 + (c5a >> 1) * 8 + 2 * t + (c5a & 1),
                 rs1[rr], rs2[rr], rs3[rr], rk12[rr]);
            ins3(un_key(n2[rr]), kt * 128 + (c5b >> 1) * 8 + 2 * t + (c5b & 1),
                 rs1[rr], rs2[rr], rs3[rr], rk12[rr]);
            ins3(un_key(n3[rr]), kt * 128 + (c5c >> 1) * 8 + 2 * t + (c5c & 1),
                 rs1[rr], rs2[rr], rs3[rr], rk12[rr]);
        }
        __syncthreads();    // all warps done with this buffer before prefetch reuses it
    }

    // merge top-3 across the 4-lane column group
#pragma unroll
    for (int rr = 0; rr < 4; rr++) {
#pragma unroll
        for (int off = 1; off <= 2; off <<= 1) {
            float o1 = __shfl_xor_sync(0xffffffffu, rs1[rr], off, 4);
            float o2 = __shfl_xor_sync(0xffffffffu, rs2[rr], off, 4);
            float o3 = __shfl_xor_sync(0xffffffffu, rs3[rr], off, 4);
            u32   oj = __shfl_xor_sync(0xffffffffu, rk12[rr], off, 4);
            int j1 = oj & 0xffff, j2 = oj >> 16;
            float a1 = rs1[rr], a2 = rs2[rr], a3 = rs3[rr];
            int ak1 = rk12[rr] & 0xffff, ak2 = rk12[rr] >> 16;
            if (lt2(o1, j1, a1, ak1)) {
                rs1[rr] = o1;
                if (lt2(a1, ak1, o2, j2)) {
                    rk12[rr] = ((u32)ak1 << 16) | (u32)j1;
                    rs2[rr] = a1; rs3[rr] = fminf(a2, o2);
                } else {
                    rk12[rr] = ((u32)j2 << 16) | (u32)j1;
                    rs2[rr] = o2; rs3[rr] = fminf(a1, o3);
                }
            } else {
                if (lt2(o1, j1, a2, ak2)) {
                    rk12[rr] = ((u32)j1 << 16) | (u32)ak1;
                    rs2[rr] = o1; rs3[rr] = fminf(a2, o2);
                } else {
                    rs3[rr] = fminf(o1, a3);
                }
            }
        }
    }
    __syncthreads();
    if (t == 0) {
#pragma unroll
        for (int rr = 0; rr < 4; rr++) {
            int L = warp * 32 + (rr >> 1) * 16 + (rr & 1) * 8 + g;
            int k1 = rk12[rr] & 0xffff;
            idx_s[L] = k1;
            if (rs2[rr] - rs1[rr] < GAP_T) {
                int tier2 = (rs3[rr] - rs1[rr] < GAP_T) ? 1 : 0;
                int pos = atomicAdd(&g_nfix, 1);
                if (pos < FIXCAP)
                    g_fixlist[pos] = make_int4(token0 + L, k1, (int)(rk12[rr] >> 16), tier2);
            }
        }
    }
    __syncthreads();

    {
        int k = idx_s[tid];
        atomicAdd(&g_counts[k], 1.0f);
        g_idx[token0 + tid]     = k;
        out_idx_f[token0 + tid] = (float)k;
    }

    // dw scatter: re-read A from global (L2-warm), v4 vector reductions.
#pragma unroll
    for (int it = 0; it < 16; it++) {
        int m   = it * 256 + tid;
        int tkn = m & 255;
        int q   = m >> 8;
        float a0 = Abase[(size_t)(q * 4 + 0) * HW + tkn];
        float a1 = Abase[(size_t)(q * 4 + 1) * HW + tkn];
        float a2 = Abase[(size_t)(q * 4 + 2) * HW + tkn];
        float a3 = Abase[(size_t)(q * 4 + 3) * HW + tkn];
        float* p = g_dw + idx_s[tkn] * 64 + q * 4;
        asm volatile("red.global.add.v4.f32 [%0], {%1, %2, %3, %4};"
                     :: "l"(p), "f"(a0), "f"(a1), "f"(a2), "f"(a3) : "memory");
    }
}

// ---------------- kernel 3b: two-tier fp64 repair ----------------
__global__ __launch_bounds__(256)
void k_fix4(const float* __restrict__ in, const float* __restrict__ w,
            float* __restrict__ out_idx_f) {
    __shared__ float xs[8][64];
    int n = g_nfix; if (n > FIXCAP) n = FIXCAP;
    const int warp = threadIdx.x >> 5;
    const int lane = threadIdx.x & 31;
    for (int i = blockIdx.x * 8 + warp; i < n; i += gridDim.x * 8) {
        int4 e = g_fixlist[i];
        const int t = e.x;
        const float* x = in + (size_t)(t >> 12) * CHW + (t & 4095);
        float xv1f = x[(size_t)lane * HW];
        float xv2f = x[(size_t)(lane + 32) * HW];

        int bk;
        if (!e.w) {
            double xv1 = (double)xv1f, xv2 = (double)xv2f;
            double d1 = xv1 * (double)w[e.y * 64 + lane]
                      + xv2 * (double)w[e.y * 64 + 32 + lane];
            double d2 = xv1 * (double)w[e.z * 64 + lane]
                      + xv2 * (double)w[e.z * 64 + 32 + lane];
#pragma unroll
            for (int off = 16; off > 0; off >>= 1) {
                d1 += __shfl_xor_sync(0xffffffffu, d1, off);
                d2 += __shfl_xor_sync(0xffffffffu, d2, off);
            }
            double s1 = g_wnh64[e.y] - d1;
            double s2 = g_wnh64[e.z] - d2;
            bk = (s2 < s1 || (s2 == s1 && e.z < e.y)) ? e.z : e.y;
        } else {
            xs[warp][lane]      = xv1f;
            xs[warp][lane + 32] = xv2f;
            __syncwarp();
            double bd = CUDART_INF;
            bk = 0x7fffffff;
            for (int jj = 0; jj < 8; jj++) {
                int    c[4];
                double acc[4] = {0.0, 0.0, 0.0, 0.0};
#pragma unroll
                for (int u = 0; u < 4; u++) c[u] = (jj + u * 8) * 32 + lane;
#pragma unroll 4
                for (int q = 0; q < 16; q++) {
                    float4 wv[4];
#pragma unroll
                    for (int u = 0; u < 4; u++)
                        wv[u] = ((const float4*)(w + c[u] * 64))[q];
#pragma unroll
                    for (int r = 0; r < 4; r++) {
                        double xv = (double)xs[warp][q * 4 + r];
#pragma unroll
                        for (int u = 0; u < 4; u++)
                            acc[u] = fma(xv, (double)((&wv[u].x)[r]), acc[u]);
                    }
                }
#pragma unroll
                for (int u = 0; u < 4; u++) {
                    double s = g_wnh64[c[u]] - acc[u];
                    if (s < bd || (s == bd && c[u] < bk)) { bd = s; bk = c[u]; }
                }
            }
#pragma unroll
            for (int off = 16; off > 0; off >>= 1) {
                double od = __shfl_xor_sync(0xffffffffu, bd, off);
                int    ok = __shfl_xor_sync(0xffffffffu, bk, off);
                if (od < bd || (od == bd && ok < bk)) { bd = od; bk = ok; }
            }
            __syncwarp();
        }

        int old = e.y;
        if (bk != old) {
            if (lane == 0) {
                g_idx[t]     = bk;
                out_idx_f[t] = (float)bk;
                atomicAdd(&g_counts[old], -1.0f);
                atomicAdd(&g_counts[bk],   1.0f);
            }
            atomicAdd(&g_dw[old * 64 + lane],      -xv1f);
            atomicAdd(&g_dw[old * 64 + 32 + lane], -xv2f);
            atomicAdd(&g_dw[bk  * 64 + lane],       xv1f);
            atomicAdd(&g_dw[bk  * 64 + 32 + lane],  xv2f);
        }
    }
}

// ---------------- kernel 4a: n = sum(cs) ----------------
__global__ void k_sum(const float* __restrict__ ecs) {
    __shared__ float red[1024];
    int k = threadIdx.x;
    red[k] = ecs[k] * 0.99f + 0.01f * g_counts[k];
    __syncthreads();
    for (int s = 512; s > 0; s >>= 1) {
        if (k < s) red[k] += red[k + s];
        __syncthreads();
    }
    if (k == 0) g_n = red[0];
}

// ---------------- kernel 4b: EMA update, fully coalesced ----------------
__global__ __launch_bounds__(256)
void k_updw(const float* __restrict__ ecs, const float* __restrict__ ew) {
    int i = blockIdx.x * 256 + threadIdx.x;
    int k = i >> 6;
    float n  = g_n;
    float cs = ecs[k] * 0.99f + 0.01f * g_counts[k];
    float csn = (cs + 1e-5f) / (n + 1024.0f * 1e-5f) * n;
    float e = ew[i] * 0.99f + 0.01f * g_dw[i];
    g_neww[i] = e / csn;
}

// ---------------- kernel 5: gather + straight-through + loss partials -------------
__global__ __launch_bounds__(256)
void k_gather(const float* __restrict__ in, float* __restrict__ out_q) {
    __shared__ float q_s[128 * 68];
    __shared__ int   idx_s[128];
    __shared__ float part[8];
    const int tid = threadIdx.x;
    const int token0 = blockIdx.x * 128;
    const int b   = token0 >> 12;
    const int hw0 = token0 & 4095;

    if (tid < 128) idx_s[tid] = g_idx[token0 + tid];
    __syncthreads();

#pragma unroll
    for (int r = 0; r < 8; r++) {
        int m  = r * 256 + tid;
        int t  = m >> 4;
        int sg = (m & 15) * 4;
        float4 v = *(const float4*)(g_neww + idx_s[t] * 64 + sg);
        *(float4*)(q_s + t * 68 + sg) = v;
    }
    __syncthreads();

    const size_t base = (size_t)b * CHW + hw0;
    float lsum = 0.f;
#pragma unroll 4
    for (int it = 0; it < 32; it++) {
        int d = it * 2 + (tid >> 7);
        int t = tid & 127;
        size_t gidx = base + (size_t)d * HW + t;
        float x  = in[gidx];
        float q  = q_s[t * 68 + d];
        float dt = q - x;
        out_q[gidx] = x + dt;
        lsum = fmaf(dt, dt, lsum);
    }
#pragma unroll
    for (int off = 16; off > 0; off >>= 1)
        lsum += __shfl_xor_sync(0xffffffffu, lsum, off);
    if ((tid & 31) == 0) part[tid >> 5] = lsum;
    __syncthreads();
    if (tid == 0) {
        float s = 0.f;
#pragma unroll
        for (int i = 0; i < 8; i++) s += part[i];
        atomicAdd(&g_loss, s);
    }
}

// ---------------- kernel 6: finalize loss ----------------
__global__ void k_final(float* out) {
    out[0] = 0.25f * (g_loss * (1.0f / 16777216.0f));
}

// ---------------- launch ----------------
extern "C" void kernel_launch(void* const* d_in, const int* in_sizes, int n_in,
                              void* d_out, int out_size) {
    const float* in  = (const float*)d_in[0];   // (64,64,64,64) NCHW
    const float* w   = (const float*)d_in[1];   // (1024,64)
    const float* ecs = (const float*)d_in[2];   // (1024,)
    const float* ew  = (const float*)d_in[3];   // (1024,64)
    float* out      = (float*)d_out;            // [loss | quantized NCHW | idx]
    float* out_q    = out + 1;
    float* out_idx  = out + 1 + Q_ELEMS;

    k_prep<<<128, 256>>>(w);
    k_pack<<<64, 256>>>(w);
    cudaFuncSetAttribute(k_argmin, cudaFuncAttributeMaxDynamicSharedMemorySize, SM_TOT);
    k_argmin<<<N_TOK / 256, 256, SM_TOT>>>(in, out_idx);
    k_fix4<<<256, 256>>>(in, w, out_idx);
    k_sum<<<1, 1024>>>(ecs);
    k_updw<<<256, 256>>>(ecs, ew);
    k_gather<<<N_TOK / 128, 256>>>(in, out_q);
    k_final<<<1, 1>>>(out);
}